// round 1
// baseline (speedup 1.0000x reference)
#include <cuda_runtime.h>
#include <cstdint>

// Problem constants
#define BB    2
#define SS    2048
#define DM    1024
#define NH    16
#define DK    64
#define MROWS (BB * SS)          // 4096

// Scratch (allocation-free rule: __device__ globals)
__device__ float g_Q[MROWS * DM];
__device__ float g_K[MROWS * DM];
__device__ float g_V[MROWS * DM];
__device__ float g_A[MROWS * DM];

// ---------------------------------------------------------------------------
// GEMM:  C[m,n] = sum_k A[m,k] * W[n,k]   (both row-major, K contiguous)
// Tiles: 128x128x8, 256 threads, 8x8 per thread.
// ---------------------------------------------------------------------------
#define TM 128
#define TN 128
#define TK 8

__global__ __launch_bounds__(256) void gemm_nt_kernel(
    const float* __restrict__ A, const float* __restrict__ W,
    float* __restrict__ C, int M, int N, int K)
{
    __shared__ float As[TK][TM];
    __shared__ float Bs[TK][TN];

    const int t  = threadIdx.x;
    const int tx = t & 15;        // 0..15  -> col group
    const int ty = t >> 4;        // 0..15  -> row group
    const int m0 = blockIdx.y * TM;
    const int n0 = blockIdx.x * TN;

    const int lrow = t >> 1;        // 0..127
    const int lk   = (t & 1) * 4;   // 0 or 4

    float acc[8][8];
#pragma unroll
    for (int i = 0; i < 8; i++)
#pragma unroll
        for (int j = 0; j < 8; j++) acc[i][j] = 0.0f;

    const float* aptr = A + (size_t)(m0 + lrow) * K + lk;
    const float* wptr = W + (size_t)(n0 + lrow) * K + lk;

    for (int k0 = 0; k0 < K; k0 += TK) {
        float4 av = *(const float4*)(aptr + k0);
        float4 bv = *(const float4*)(wptr + k0);
        __syncthreads();
        As[lk + 0][lrow] = av.x;
        As[lk + 1][lrow] = av.y;
        As[lk + 2][lrow] = av.z;
        As[lk + 3][lrow] = av.w;
        Bs[lk + 0][lrow] = bv.x;
        Bs[lk + 1][lrow] = bv.y;
        Bs[lk + 2][lrow] = bv.z;
        Bs[lk + 3][lrow] = bv.w;
        __syncthreads();

#pragma unroll
        for (int kk = 0; kk < TK; kk++) {
            float4 a0 = *(const float4*)&As[kk][ty * 8];
            float4 a1 = *(const float4*)&As[kk][ty * 8 + 4];
            float4 b0 = *(const float4*)&Bs[kk][tx * 8];
            float4 b1 = *(const float4*)&Bs[kk][tx * 8 + 4];
            float a[8] = {a0.x, a0.y, a0.z, a0.w, a1.x, a1.y, a1.z, a1.w};
            float b[8] = {b0.x, b0.y, b0.z, b0.w, b1.x, b1.y, b1.z, b1.w};
#pragma unroll
            for (int i = 0; i < 8; i++)
#pragma unroll
                for (int j = 0; j < 8; j++)
                    acc[i][j] = fmaf(a[i], b[j], acc[i][j]);
        }
    }

#pragma unroll
    for (int i = 0; i < 8; i++) {
        float* crow = C + (size_t)(m0 + ty * 8 + i) * N + n0 + tx * 8;
        float4 c0 = {acc[i][0], acc[i][1], acc[i][2], acc[i][3]};
        float4 c1 = {acc[i][4], acc[i][5], acc[i][6], acc[i][7]};
        *(float4*)(crow)     = c0;
        *(float4*)(crow + 4) = c1;
    }
}

// ---------------------------------------------------------------------------
// RoPE (applied in-place to Q and K).
// One thread per (row, pair): pair i -> cols (h*64 + 2i, h*64 + 2i + 1)
// ---------------------------------------------------------------------------
__global__ void rope_kernel(float* __restrict__ Q, float* __restrict__ K,
                            const int* __restrict__ pos)
{
    int idx = blockIdx.x * blockDim.x + threadIdx.x;   // 0 .. MROWS*512-1
    if (idx >= MROWS * (DM / 2)) return;
    int row = idx >> 9;          // /512
    int pr  = idx & 511;         // pair index in row (= h*32 + i)
    int i   = pr & 31;           // pair within head
    int col = 2 * pr;            // = h*64 + 2i

    float p = (float)pos[row];
    // inv_freq = theta^(-2i/dk) = 2^(-2i * log2(theta)/dk)
    float invf = exp2f(-(float)(2 * i) * (13.287712379549449f / 64.0f));
    float ang  = p * invf;
    float s, c;
    sincosf(ang, &s, &c);

    float2* qp = (float2*)&Q[(size_t)row * DM + col];
    float2* kp = (float2*)&K[(size_t)row * DM + col];
    float2 q = *qp;
    float2 k = *kp;
    float2 qo = {q.x * c - q.y * s, q.x * s + q.y * c};
    float2 ko = {k.x * c - k.y * s, k.x * s + k.y * c};
    *qp = qo;
    *kp = ko;
}

// ---------------------------------------------------------------------------
// Flash attention (fp32, causal). One block per (q-tile of 64, head, batch).
// 256 threads. Online softmax. Shared layout (pad 68 to break bank conflicts):
//   Qt[d][r]  (Q^T, pre-scaled)    Kt[d][c]  (K^T)
//   Vs[kc][d]                      Pt[kc][r] (P^T)
// ---------------------------------------------------------------------------
#define ATT_PAD 68
#define ATT_SMEM (4 * 64 * ATT_PAD * 4)   // 69632 bytes

__global__ __launch_bounds__(256) void attn_kernel(
    const float* __restrict__ Q, const float* __restrict__ K,
    const float* __restrict__ V, float* __restrict__ O)
{
    extern __shared__ float sh[];
    float (*Qt)[ATT_PAD] = (float(*)[ATT_PAD])(sh);
    float (*Kt)[ATT_PAD] = (float(*)[ATT_PAD])(sh + 64 * ATT_PAD);
    float (*Vs)[ATT_PAD] = (float(*)[ATT_PAD])(sh + 2 * 64 * ATT_PAD);
    float (*Pt)[ATT_PAD] = (float(*)[ATT_PAD])(sh + 3 * 64 * ATT_PAD);

    const int b  = blockIdx.z;
    const int h  = blockIdx.y;
    const int q0 = blockIdx.x * 64;
    const int t  = threadIdx.x;
    const int tx = t & 15;          // col group (kc for S, d for O)
    const int ty = t >> 4;          // row group
    const int lr = t >> 2;          // load row 0..63
    const int ld = (t & 3) * 16;    // load d-offset 0/16/32/48

    const float scale = 0.125f;     // 1/sqrt(64)

    // Load Q tile transposed, pre-scaled
    {
        const float* qg = &Q[(size_t)(b * SS + q0 + lr) * DM + h * DK + ld];
#pragma unroll
        for (int u = 0; u < 4; u++) {
            float4 v = *(const float4*)&qg[u * 4];
            Qt[ld + u * 4 + 0][lr] = v.x * scale;
            Qt[ld + u * 4 + 1][lr] = v.y * scale;
            Qt[ld + u * 4 + 2][lr] = v.z * scale;
            Qt[ld + u * 4 + 3][lr] = v.w * scale;
        }
    }

    float oacc[4][4];
#pragma unroll
    for (int i = 0; i < 4; i++)
#pragma unroll
        for (int j = 0; j < 4; j++) oacc[i][j] = 0.0f;
    float m_i[4] = {-INFINITY, -INFINITY, -INFINITY, -INFINITY};
    float l_i[4] = {0.0f, 0.0f, 0.0f, 0.0f};

    const int ntiles = q0 / 64 + 1;
    for (int kt = 0; kt < ntiles; kt++) {
        const int k0 = kt * 64;
        __syncthreads();   // prior O-phase done; safe to overwrite Kt/Vs

        // Load K transposed + V natural
        {
            const float* kg = &K[(size_t)(b * SS + k0 + lr) * DM + h * DK + ld];
            const float* vg = &V[(size_t)(b * SS + k0 + lr) * DM + h * DK + ld];
#pragma unroll
            for (int u = 0; u < 4; u++) {
                float4 kv = *(const float4*)&kg[u * 4];
                Kt[ld + u * 4 + 0][lr] = kv.x;
                Kt[ld + u * 4 + 1][lr] = kv.y;
                Kt[ld + u * 4 + 2][lr] = kv.z;
                Kt[ld + u * 4 + 3][lr] = kv.w;
                float4 vv = *(const float4*)&vg[u * 4];
                *(float4*)&Vs[lr][ld + u * 4] = vv;
            }
        }
        __syncthreads();

        // S = (Q*scale) K^T  (outer-product over d)
        float s[4][4];
#pragma unroll
        for (int i = 0; i < 4; i++)
#pragma unroll
            for (int j = 0; j < 4; j++) s[i][j] = 0.0f;

#pragma unroll 8
        for (int d = 0; d < 64; d++) {
            float4 qv = *(const float4*)&Qt[d][ty * 4];
            float4 kv = *(const float4*)&Kt[d][tx * 4];
            float qa[4] = {qv.x, qv.y, qv.z, qv.w};
            float ka[4] = {kv.x, kv.y, kv.z, kv.w};
#pragma unroll
            for (int i = 0; i < 4; i++)
#pragma unroll
                for (int j = 0; j < 4; j++)
                    s[i][j] = fmaf(qa[i], ka[j], s[i][j]);
        }

        // Causal mask on the diagonal tile (k0 == q0 there)
        if (kt == ntiles - 1) {
#pragma unroll
            for (int i = 0; i < 4; i++)
#pragma unroll
                for (int j = 0; j < 4; j++)
                    if (tx * 4 + j > ty * 4 + i) s[i][j] = -INFINITY;
        }

        // Online softmax update
        float pbuf[4][4];
#pragma unroll
        for (int i = 0; i < 4; i++) {
            float mx = fmaxf(fmaxf(s[i][0], s[i][1]), fmaxf(s[i][2], s[i][3]));
#pragma unroll
            for (int off = 8; off >= 1; off >>= 1)
                mx = fmaxf(mx, __shfl_xor_sync(0xffffffffu, mx, off, 16));
            float mnew  = fmaxf(m_i[i], mx);
            float alpha = __expf(m_i[i] - mnew);
            float rs = 0.0f;
#pragma unroll
            for (int j = 0; j < 4; j++) {
                pbuf[i][j] = __expf(s[i][j] - mnew);
                rs += pbuf[i][j];
            }
#pragma unroll
            for (int off = 8; off >= 1; off >>= 1)
                rs += __shfl_xor_sync(0xffffffffu, rs, off, 16);
            l_i[i] = l_i[i] * alpha + rs;
            m_i[i] = mnew;
#pragma unroll
            for (int j = 0; j < 4; j++) oacc[i][j] *= alpha;
        }

        // Store P transposed: Pt[kc][r]
#pragma unroll
        for (int j = 0; j < 4; j++) {
            float4 pv = {pbuf[0][j], pbuf[1][j], pbuf[2][j], pbuf[3][j]};
            *(float4*)&Pt[tx * 4 + j][ty * 4] = pv;
        }
        __syncthreads();

        // O += P V  (outer-product over kc)
#pragma unroll 8
        for (int kc = 0; kc < 64; kc++) {
            float4 pv = *(const float4*)&Pt[kc][ty * 4];
            float4 vv = *(const float4*)&Vs[kc][tx * 4];
            float pa[4] = {pv.x, pv.y, pv.z, pv.w};
            float va[4] = {vv.x, vv.y, vv.z, vv.w};
#pragma unroll
            for (int i = 0; i < 4; i++)
#pragma unroll
                for (int j = 0; j < 4; j++)
                    oacc[i][j] = fmaf(pa[i], va[j], oacc[i][j]);
        }
    }

    // Normalize + write [b, s, h*dk + d]
#pragma unroll
    for (int i = 0; i < 4; i++) {
        float inv = 1.0f / l_i[i];
        float4 ov = {oacc[i][0] * inv, oacc[i][1] * inv,
                     oacc[i][2] * inv, oacc[i][3] * inv};
        *(float4*)&O[(size_t)(b * SS + q0 + ty * 4 + i) * DM + h * DK + tx * 4] = ov;
    }
}

// ---------------------------------------------------------------------------
// Launch
// ---------------------------------------------------------------------------
extern "C" void kernel_launch(void* const* d_in, const int* in_sizes, int n_in,
                              void* d_out, int out_size)
{
    const float* x  = (const float*)d_in[0];
    const int*   tp = (const int*)d_in[1];
    const float* Wq = (const float*)d_in[2];
    const float* Wk = (const float*)d_in[3];
    const float* Wv = (const float*)d_in[4];
    const float* Wo = (const float*)d_in[5];
    float* out = (float*)d_out;

    float *gq, *gk, *gv, *ga;
    cudaGetSymbolAddress((void**)&gq, g_Q);
    cudaGetSymbolAddress((void**)&gk, g_K);
    cudaGetSymbolAddress((void**)&gv, g_V);
    cudaGetSymbolAddress((void**)&ga, g_A);

    dim3 ggrid(DM / TN, MROWS / TM);   // (8, 32)

    gemm_nt_kernel<<<ggrid, 256>>>(x, Wq, gq, MROWS, DM, DM);
    gemm_nt_kernel<<<ggrid, 256>>>(x, Wk, gk, MROWS, DM, DM);
    gemm_nt_kernel<<<ggrid, 256>>>(x, Wv, gv, MROWS, DM, DM);

    int rope_threads = MROWS * (DM / 2);
    rope_kernel<<<(rope_threads + 255) / 256, 256>>>(gq, gk, tp);

    cudaFuncSetAttribute(attn_kernel,
                         cudaFuncAttributeMaxDynamicSharedMemorySize, ATT_SMEM);
    attn_kernel<<<dim3(SS / 64, NH, BB), 256, ATT_SMEM>>>(gq, gk, gv, ga);

    gemm_nt_kernel<<<ggrid, 256>>>(ga, Wo, out, MROWS, DM, DM);
}

// round 3
// speedup vs baseline: 1.7921x; 1.7921x over previous
#include <cuda_runtime.h>
#include <cstdint>

// Problem constants
#define BB    2
#define SS    2048
#define DM    1024
#define NH    16
#define DK    64
#define MROWS (BB * SS)          // 4096

// Scratch (allocation-free rule: __device__ globals)
__device__ float g_Q[MROWS * DM];
__device__ float g_K[MROWS * DM];
__device__ float g_V[MROWS * DM];
__device__ float g_A[MROWS * DM];

// ===========================================================================
// Helpers
// ===========================================================================
__device__ __forceinline__ uint32_t smem_u32(const void* p) {
    uint32_t a;
    asm("{ .reg .u64 t; cvta.to.shared.u64 t, %1; cvt.u32.u64 %0, t; }"
        : "=r"(a) : "l"(p));
    return a;
}
__device__ __forceinline__ void cp16(uint32_t dst, const void* src) {
    asm volatile("cp.async.cg.shared.global [%0], [%1], 16;"
                 :: "r"(dst), "l"(src));
}
#define CP_COMMIT() asm volatile("cp.async.commit_group;" ::: "memory")
#define CP_WAIT1()  asm volatile("cp.async.wait_group 1;" ::: "memory")

__device__ __forceinline__ uint32_t f2tf32(float f) {
    uint32_t r;
    asm("cvt.rna.tf32.f32 %0, %1;" : "=r"(r) : "f"(f));
    return r;
}

// mma.sync m16n8k8 tf32: D(4) = A(4) * B(2) + C(4)
__device__ __forceinline__ void mma_tf32(float c[4],
                                         const uint32_t a[4],
                                         const uint32_t b[2]) {
    asm volatile(
        "mma.sync.aligned.m16n8k8.row.col.f32.tf32.tf32.f32 "
        "{%0,%1,%2,%3}, {%4,%5,%6,%7}, {%8,%9}, {%0,%1,%2,%3};"
        : "+f"(c[0]), "+f"(c[1]), "+f"(c[2]), "+f"(c[3])
        : "r"(a[0]), "r"(a[1]), "r"(a[2]), "r"(a[3]),
          "r"(b[0]), "r"(b[1]));
}

// ===========================================================================
// tf32 mma.sync GEMM:  C[m,n] = sum_k A[m,k] * W[n,k]  (both row-major)
// 128x128 CTA tile, K-stage 32 floats, 2-stage cp.async double buffer.
// 256 threads = 8 warps (2 M x 4 N), warp tile 64x32.
// Smem row stride = 36 floats (conflict-free fragment loads, 16B aligned).
// gridDim.z selects (W, C) so QKV fuses into one launch.
// ===========================================================================
#define GT_THREADS 256
#define KT 32
#define SROW 36
#define TILE_FLOATS (128 * SROW)               // 4608
#define GEMM_SMEM (4 * TILE_FLOATS * 4)        // 73728 bytes

__device__ __forceinline__ void load_tile(uint32_t smem_dst,
                                          const float* __restrict__ g,
                                          int tid) {
    // 128 rows x 32 floats; dest stride SROW floats.
#pragma unroll
    for (int i = 0; i < 4; i++) {
        int idx = tid + i * GT_THREADS;   // 0..1023
        int row = idx >> 3;
        int c   = idx & 7;
        cp16(smem_dst + (uint32_t)(row * SROW * 4 + c * 16),
             (const char*)(g + (size_t)row * DM) + c * 16);
    }
}

__global__ __launch_bounds__(GT_THREADS) void gemm_tc_kernel(
    const float* __restrict__ A,
    const float* __restrict__ W0, const float* __restrict__ W1,
    const float* __restrict__ W2,
    float* __restrict__ C0, float* __restrict__ C1, float* __restrict__ C2)
{
    extern __shared__ float sh[];
    float* As[2] = { sh,                  sh + 2 * TILE_FLOATS };
    float* Bs[2] = { sh + TILE_FLOATS,    sh + 3 * TILE_FLOATS };
    uint32_t sbA[2] = { smem_u32(As[0]), smem_u32(As[1]) };
    uint32_t sbB[2] = { smem_u32(Bs[0]), smem_u32(Bs[1]) };

    const int tid = threadIdx.x;
    const int wid = tid >> 5;
    const int lid = tid & 31;
    const int g8  = lid >> 2;       // groupID 0..7
    const int tig = lid & 3;        // thread-in-group 0..3
    const int wm0 = (wid & 1) * 64; // warp M offset in tile
    const int wn0 = (wid >> 1) * 32;// warp N offset in tile

    const int m0 = blockIdx.y * 128;
    const int n0 = blockIdx.x * 128;
    const float* W = (blockIdx.z == 0) ? W0 : (blockIdx.z == 1) ? W1 : W2;
    float*       C = (blockIdx.z == 0) ? C0 : (blockIdx.z == 1) ? C1 : C2;

    const float* Abase = A + (size_t)m0 * DM;
    const float* Wbase = W + (size_t)n0 * DM;

    float acc[4][4][4];   // [mtile][ntile][reg]
#pragma unroll
    for (int i = 0; i < 4; i++)
#pragma unroll
        for (int j = 0; j < 4; j++)
#pragma unroll
            for (int r = 0; r < 4; r++) acc[i][j][r] = 0.0f;

    // Prologue: fill both stages
    load_tile(sbA[0], Abase, tid);
    load_tile(sbB[0], Wbase, tid);
    CP_COMMIT();
    load_tile(sbA[1], Abase + KT, tid);
    load_tile(sbB[1], Wbase + KT, tid);
    CP_COMMIT();

    const int NIT = DM / KT;   // 32
    for (int it = 0; it < NIT; it++) {
        const int s = it & 1;
        CP_WAIT1();
        __syncthreads();

        const float* at = As[s];
        const float* bt = Bs[s];
#pragma unroll
        for (int ks = 0; ks < 4; ks++) {
            const int k0 = ks * 8;
            // A fragments: 4 mtiles
            uint32_t af[4][4];
#pragma unroll
            for (int mt = 0; mt < 4; mt++) {
                const float* ap = at + (wm0 + mt * 16 + g8) * SROW + k0 + tig;
                af[mt][0] = f2tf32(ap[0]);
                af[mt][1] = f2tf32(ap[8 * SROW]);
                af[mt][2] = f2tf32(ap[4]);
                af[mt][3] = f2tf32(ap[8 * SROW + 4]);
            }
            // B fragments: 4 ntiles
            uint32_t bf[4][2];
#pragma unroll
            for (int nt = 0; nt < 4; nt++) {
                const float* bp = bt + (wn0 + nt * 8 + g8) * SROW + k0 + tig;
                bf[nt][0] = f2tf32(bp[0]);
                bf[nt][1] = f2tf32(bp[4]);
            }
#pragma unroll
            for (int mt = 0; mt < 4; mt++)
#pragma unroll
                for (int nt = 0; nt < 4; nt++)
                    mma_tf32(acc[mt][nt], af[mt], bf[nt]);
        }
        __syncthreads();

        if (it + 2 < NIT) {
            const int k0 = (it + 2) * KT;
            load_tile(sbA[s], Abase + k0, tid);
            load_tile(sbB[s], Wbase + k0, tid);
        }
        CP_COMMIT();   // uniform group accounting (empty group OK)
    }

    // Epilogue: write accumulators (float2 per row-half per tile)
#pragma unroll
    for (int mt = 0; mt < 4; mt++) {
#pragma unroll
        for (int half = 0; half < 2; half++) {
            const int row = m0 + wm0 + mt * 16 + g8 + half * 8;
            float* crow = C + (size_t)row * DM + n0 + wn0;
#pragma unroll
            for (int nt = 0; nt < 4; nt++) {
                float2 v = { acc[mt][nt][half * 2 + 0],
                             acc[mt][nt][half * 2 + 1] };
                *(float2*)(crow + nt * 8 + tig * 2) = v;
            }
        }
    }
}

// ---------------------------------------------------------------------------
// RoPE (applied in-place to Q and K).
// ---------------------------------------------------------------------------
__global__ void rope_kernel(float* __restrict__ Q, float* __restrict__ K,
                            const int* __restrict__ pos)
{
    int idx = blockIdx.x * blockDim.x + threadIdx.x;
    if (idx >= MROWS * (DM / 2)) return;
    int row = idx >> 9;
    int pr  = idx & 511;
    int i   = pr & 31;
    int col = 2 * pr;

    float p = (float)pos[row];
    float invf = exp2f(-(float)(2 * i) * (13.287712379549449f / 64.0f));
    float ang  = p * invf;
    float s, c;
    sincosf(ang, &s, &c);

    float2* qp = (float2*)&Q[(size_t)row * DM + col];
    float2* kp = (float2*)&K[(size_t)row * DM + col];
    float2 q = *qp;
    float2 k = *kp;
    float2 qo = {q.x * c - q.y * s, q.x * s + q.y * c};
    float2 ko = {k.x * c - k.y * s, k.x * s + k.y * c};
    *qp = qo;
    *kp = ko;
}

// ---------------------------------------------------------------------------
// Flash attention (fp32, causal). One block per (q-tile of 64, head, batch).
// ---------------------------------------------------------------------------
#define ATT_PAD 68
#define ATT_SMEM (4 * 64 * ATT_PAD * 4)

__global__ __launch_bounds__(256) void attn_kernel(
    const float* __restrict__ Q, const float* __restrict__ K,
    const float* __restrict__ V, float* __restrict__ O)
{
    extern __shared__ float shf[];
    float (*Qt)[ATT_PAD] = (float(*)[ATT_PAD])(shf);
    float (*Kt)[ATT_PAD] = (float(*)[ATT_PAD])(shf + 64 * ATT_PAD);
    float (*Vs)[ATT_PAD] = (float(*)[ATT_PAD])(shf + 2 * 64 * ATT_PAD);
    float (*Pt)[ATT_PAD] = (float(*)[ATT_PAD])(shf + 3 * 64 * ATT_PAD);

    const int b  = blockIdx.z;
    const int h  = blockIdx.y;
    const int q0 = blockIdx.x * 64;
    const int t  = threadIdx.x;
    const int tx = t & 15;
    const int ty = t >> 4;
    const int lr = t >> 2;
    const int ld = (t & 3) * 16;

    const float scale = 0.125f;

    {
        const float* qg = &Q[(size_t)(b * SS + q0 + lr) * DM + h * DK + ld];
#pragma unroll
        for (int u = 0; u < 4; u++) {
            float4 v = *(const float4*)&qg[u * 4];
            Qt[ld + u * 4 + 0][lr] = v.x * scale;
            Qt[ld + u * 4 + 1][lr] = v.y * scale;
            Qt[ld + u * 4 + 2][lr] = v.z * scale;
            Qt[ld + u * 4 + 3][lr] = v.w * scale;
        }
    }

    float oacc[4][4];
#pragma unroll
    for (int i = 0; i < 4; i++)
#pragma unroll
        for (int j = 0; j < 4; j++) oacc[i][j] = 0.0f;
    float m_i[4] = {-INFINITY, -INFINITY, -INFINITY, -INFINITY};
    float l_i[4] = {0.0f, 0.0f, 0.0f, 0.0f};

    const int ntiles = q0 / 64 + 1;
    for (int kt = 0; kt < ntiles; kt++) {
        const int k0 = kt * 64;
        __syncthreads();

        {
            const float* kg = &K[(size_t)(b * SS + k0 + lr) * DM + h * DK + ld];
            const float* vg = &V[(size_t)(b * SS + k0 + lr) * DM + h * DK + ld];
#pragma unroll
            for (int u = 0; u < 4; u++) {
                float4 kv = *(const float4*)&kg[u * 4];
                Kt[ld + u * 4 + 0][lr] = kv.x;
                Kt[ld + u * 4 + 1][lr] = kv.y;
                Kt[ld + u * 4 + 2][lr] = kv.z;
                Kt[ld + u * 4 + 3][lr] = kv.w;
                float4 vv = *(const float4*)&vg[u * 4];
                *(float4*)&Vs[lr][ld + u * 4] = vv;
            }
        }
        __syncthreads();

        float s[4][4];
#pragma unroll
        for (int i = 0; i < 4; i++)
#pragma unroll
            for (int j = 0; j < 4; j++) s[i][j] = 0.0f;

#pragma unroll 8
        for (int d = 0; d < 64; d++) {
            float4 qv = *(const float4*)&Qt[d][ty * 4];
            float4 kv = *(const float4*)&Kt[d][tx * 4];
            float qa[4] = {qv.x, qv.y, qv.z, qv.w};
            float ka[4] = {kv.x, kv.y, kv.z, kv.w};
#pragma unroll
            for (int i = 0; i < 4; i++)
#pragma unroll
                for (int j = 0; j < 4; j++)
                    s[i][j] = fmaf(qa[i], ka[j], s[i][j]);
        }

        if (kt == ntiles - 1) {
#pragma unroll
            for (int i = 0; i < 4; i++)
#pragma unroll
                for (int j = 0; j < 4; j++)
                    if (tx * 4 + j > ty * 4 + i) s[i][j] = -INFINITY;
        }

        float pbuf[4][4];
#pragma unroll
        for (int i = 0; i < 4; i++) {
            float mx = fmaxf(fmaxf(s[i][0], s[i][1]), fmaxf(s[i][2], s[i][3]));
#pragma unroll
            for (int off = 8; off >= 1; off >>= 1)
                mx = fmaxf(mx, __shfl_xor_sync(0xffffffffu, mx, off, 16));
            float mnew  = fmaxf(m_i[i], mx);
            float alpha = __expf(m_i[i] - mnew);
            float rs = 0.0f;
#pragma unroll
            for (int j = 0; j < 4; j++) {
                pbuf[i][j] = __expf(s[i][j] - mnew);
                rs += pbuf[i][j];
            }
#pragma unroll
            for (int off = 8; off >= 1; off >>= 1)
                rs += __shfl_xor_sync(0xffffffffu, rs, off, 16);
            l_i[i] = l_i[i] * alpha + rs;
            m_i[i] = mnew;
#pragma unroll
            for (int j = 0; j < 4; j++) oacc[i][j] *= alpha;
        }

#pragma unroll
        for (int j = 0; j < 4; j++) {
            float4 pv = {pbuf[0][j], pbuf[1][j], pbuf[2][j], pbuf[3][j]};
            *(float4*)&Pt[tx * 4 + j][ty * 4] = pv;
        }
        __syncthreads();

#pragma unroll 8
        for (int kc = 0; kc < 64; kc++) {
            float4 pv = *(const float4*)&Pt[kc][ty * 4];
            float4 vv = *(const float4*)&Vs[kc][tx * 4];
            float pa[4] = {pv.x, pv.y, pv.z, pv.w};
            float va[4] = {vv.x, vv.y, vv.z, vv.w};
#pragma unroll
            for (int i = 0; i < 4; i++)
#pragma unroll
                for (int j = 0; j < 4; j++)
                    oacc[i][j] = fmaf(pa[i], va[j], oacc[i][j]);
        }
    }

#pragma unroll
    for (int i = 0; i < 4; i++) {
        float inv = 1.0f / l_i[i];
        float4 ov = {oacc[i][0] * inv, oacc[i][1] * inv,
                     oacc[i][2] * inv, oacc[i][3] * inv};
        *(float4*)&O[(size_t)(b * SS + q0 + ty * 4 + i) * DM + h * DK + tx * 4] = ov;
    }
}

// ---------------------------------------------------------------------------
// Launch
// ---------------------------------------------------------------------------
extern "C" void kernel_launch(void* const* d_in, const int* in_sizes, int n_in,
                              void* d_out, int out_size)
{
    const float* x  = (const float*)d_in[0];
    const int*   tp = (const int*)d_in[1];
    const float* Wq = (const float*)d_in[2];
    const float* Wk = (const float*)d_in[3];
    const float* Wv = (const float*)d_in[4];
    const float* Wo = (const float*)d_in[5];
    float* out = (float*)d_out;

    float *gq, *gk, *gv, *ga;
    cudaGetSymbolAddress((void**)&gq, g_Q);
    cudaGetSymbolAddress((void**)&gk, g_K);
    cudaGetSymbolAddress((void**)&gv, g_V);
    cudaGetSymbolAddress((void**)&ga, g_A);

    cudaFuncSetAttribute(gemm_tc_kernel,
                         cudaFuncAttributeMaxDynamicSharedMemorySize, GEMM_SMEM);
    cudaFuncSetAttribute(attn_kernel,
                         cudaFuncAttributeMaxDynamicSharedMemorySize, ATT_SMEM);

    // Fused QKV projection (z picks the weight/output)
    gemm_tc_kernel<<<dim3(DM / 128, MROWS / 128, 3), GT_THREADS, GEMM_SMEM>>>(
        x, Wq, Wk, Wv, gq, gk, gv);

    int rope_threads = MROWS * (DM / 2);
    rope_kernel<<<(rope_threads + 255) / 256, 256>>>(gq, gk, tp);

    attn_kernel<<<dim3(SS / 64, NH, BB), 256, ATT_SMEM>>>(gq, gk, gv, ga);

    // Output projection
    gemm_tc_kernel<<<dim3(DM / 128, MROWS / 128, 1), GT_THREADS, GEMM_SMEM>>>(
        ga, Wo, Wo, Wo, out, out, out);
}

// round 4
// speedup vs baseline: 3.3777x; 1.8848x over previous
#include <cuda_runtime.h>
#include <cstdint>

// Problem constants
#define BB    2
#define SS    2048
#define DM    1024
#define NH    16
#define DK    64
#define MROWS (BB * SS)          // 4096

// Scratch (allocation-free rule: __device__ globals)
__device__ float g_Q[MROWS * DM];
__device__ float g_K[MROWS * DM];
__device__ float g_V[MROWS * DM];
__device__ float g_A[MROWS * DM];

// ===========================================================================
// Helpers
// ===========================================================================
__device__ __forceinline__ uint32_t smem_u32(const void* p) {
    uint32_t a;
    asm("{ .reg .u64 t; cvta.to.shared.u64 t, %1; cvt.u32.u64 %0, t; }"
        : "=r"(a) : "l"(p));
    return a;
}
__device__ __forceinline__ void cp16(uint32_t dst, const void* src) {
    asm volatile("cp.async.cg.shared.global [%0], [%1], 16;"
                 :: "r"(dst), "l"(src));
}
#define CP_COMMIT() asm volatile("cp.async.commit_group;" ::: "memory")
#define CP_WAIT1()  asm volatile("cp.async.wait_group 1;" ::: "memory")

__device__ __forceinline__ uint32_t f2tf32(float f) {
    uint32_t r;
    asm("cvt.rna.tf32.f32 %0, %1;" : "=r"(r) : "f"(f));
    return r;
}
__device__ __forceinline__ float f2tf32f(float f) {
    return __uint_as_float(f2tf32(f));
}

// mma.sync m16n8k8 tf32: D(4) = A(4) * B(2) + C(4)
__device__ __forceinline__ void mma_tf32(float c[4],
                                         const uint32_t a[4],
                                         const uint32_t b[2]) {
    asm volatile(
        "mma.sync.aligned.m16n8k8.row.col.f32.tf32.tf32.f32 "
        "{%0,%1,%2,%3}, {%4,%5,%6,%7}, {%8,%9}, {%0,%1,%2,%3};"
        : "+f"(c[0]), "+f"(c[1]), "+f"(c[2]), "+f"(c[3])
        : "r"(a[0]), "r"(a[1]), "r"(a[2]), "r"(a[3]),
          "r"(b[0]), "r"(b[1]));
}

// ===========================================================================
// tf32 mma.sync GEMM:  C[m,n] = sum_k A[m,k] * W[n,k]  (both row-major)
// ===========================================================================
#define GT_THREADS 256
#define KT 32
#define SROW 36
#define TILE_FLOATS (128 * SROW)               // 4608
#define GEMM_SMEM (4 * TILE_FLOATS * 4)        // 73728 bytes

__device__ __forceinline__ void load_tile(uint32_t smem_dst,
                                          const float* __restrict__ g,
                                          int tid) {
#pragma unroll
    for (int i = 0; i < 4; i++) {
        int idx = tid + i * GT_THREADS;   // 0..1023
        int row = idx >> 3;
        int c   = idx & 7;
        cp16(smem_dst + (uint32_t)(row * SROW * 4 + c * 16),
             (const char*)(g + (size_t)row * DM) + c * 16);
    }
}

__global__ __launch_bounds__(GT_THREADS) void gemm_tc_kernel(
    const float* __restrict__ A,
    const float* __restrict__ W0, const float* __restrict__ W1,
    const float* __restrict__ W2,
    float* __restrict__ C0, float* __restrict__ C1, float* __restrict__ C2)
{
    extern __shared__ float sh[];
    float* As[2] = { sh,                  sh + 2 * TILE_FLOATS };
    float* Bs[2] = { sh + TILE_FLOATS,    sh + 3 * TILE_FLOATS };
    uint32_t sbA[2] = { smem_u32(As[0]), smem_u32(As[1]) };
    uint32_t sbB[2] = { smem_u32(Bs[0]), smem_u32(Bs[1]) };

    const int tid = threadIdx.x;
    const int wid = tid >> 5;
    const int lid = tid & 31;
    const int g8  = lid >> 2;
    const int tig = lid & 3;
    const int wm0 = (wid & 1) * 64;
    const int wn0 = (wid >> 1) * 32;

    const int m0 = blockIdx.y * 128;
    const int n0 = blockIdx.x * 128;
    const float* W = (blockIdx.z == 0) ? W0 : (blockIdx.z == 1) ? W1 : W2;
    float*       C = (blockIdx.z == 0) ? C0 : (blockIdx.z == 1) ? C1 : C2;

    const float* Abase = A + (size_t)m0 * DM;
    const float* Wbase = W + (size_t)n0 * DM;

    float acc[4][4][4];
#pragma unroll
    for (int i = 0; i < 4; i++)
#pragma unroll
        for (int j = 0; j < 4; j++)
#pragma unroll
            for (int r = 0; r < 4; r++) acc[i][j][r] = 0.0f;

    load_tile(sbA[0], Abase, tid);
    load_tile(sbB[0], Wbase, tid);
    CP_COMMIT();
    load_tile(sbA[1], Abase + KT, tid);
    load_tile(sbB[1], Wbase + KT, tid);
    CP_COMMIT();

    const int NIT = DM / KT;   // 32
    for (int it = 0; it < NIT; it++) {
        const int s = it & 1;
        CP_WAIT1();
        __syncthreads();

        const float* at = As[s];
        const float* bt = Bs[s];
#pragma unroll
        for (int ks = 0; ks < 4; ks++) {
            const int k0 = ks * 8;
            uint32_t af[4][4];
#pragma unroll
            for (int mt = 0; mt < 4; mt++) {
                const float* ap = at + (wm0 + mt * 16 + g8) * SROW + k0 + tig;
                af[mt][0] = f2tf32(ap[0]);
                af[mt][1] = f2tf32(ap[8 * SROW]);
                af[mt][2] = f2tf32(ap[4]);
                af[mt][3] = f2tf32(ap[8 * SROW + 4]);
            }
            uint32_t bf[4][2];
#pragma unroll
            for (int nt = 0; nt < 4; nt++) {
                const float* bp = bt + (wn0 + nt * 8 + g8) * SROW + k0 + tig;
                bf[nt][0] = f2tf32(bp[0]);
                bf[nt][1] = f2tf32(bp[4]);
            }
#pragma unroll
            for (int mt = 0; mt < 4; mt++)
#pragma unroll
                for (int nt = 0; nt < 4; nt++)
                    mma_tf32(acc[mt][nt], af[mt], bf[nt]);
        }
        __syncthreads();

        if (it + 2 < NIT) {
            const int k0 = (it + 2) * KT;
            load_tile(sbA[s], Abase + k0, tid);
            load_tile(sbB[s], Wbase + k0, tid);
        }
        CP_COMMIT();
    }

#pragma unroll
    for (int mt = 0; mt < 4; mt++) {
#pragma unroll
        for (int half = 0; half < 2; half++) {
            const int row = m0 + wm0 + mt * 16 + g8 + half * 8;
            float* crow = C + (size_t)row * DM + n0 + wn0;
#pragma unroll
            for (int nt = 0; nt < 4; nt++) {
                float2 v = { acc[mt][nt][half * 2 + 0],
                             acc[mt][nt][half * 2 + 1] };
                *(float2*)(crow + nt * 8 + tig * 2) = v;
            }
        }
    }
}

// ---------------------------------------------------------------------------
// RoPE (applied in-place to Q and K).
// ---------------------------------------------------------------------------
__global__ void rope_kernel(float* __restrict__ Q, float* __restrict__ K,
                            const int* __restrict__ pos)
{
    int idx = blockIdx.x * blockDim.x + threadIdx.x;
    if (idx >= MROWS * (DM / 2)) return;
    int row = idx >> 9;
    int pr  = idx & 511;
    int i   = pr & 31;
    int col = 2 * pr;

    float p = (float)pos[row];
    float invf = exp2f(-(float)(2 * i) * (13.287712379549449f / 64.0f));
    float ang  = p * invf;
    float s, c;
    sincosf(ang, &s, &c);

    float2* qp = (float2*)&Q[(size_t)row * DM + col];
    float2* kp = (float2*)&K[(size_t)row * DM + col];
    float2 q = *qp;
    float2 k = *kp;
    float2 qo = {q.x * c - q.y * s, q.x * s + q.y * c};
    float2 ko = {k.x * c - k.y * s, k.x * s + k.y * c};
    *qp = qo;
    *kp = ko;
}

// ===========================================================================
// Flash attention with tf32 mma.sync.
// CTA: 128 q-rows x one (head, batch). 256 threads = 8 warps, warp owns
// m16 rows. kv tiles of 128. K in smem [kv][64] stride 68 (conflict-free
// B-frag reads); V transposed [d][kv] stride 133; P per-warp [16][132].
// All smem values stored pre-rounded to tf32 bits.
// ===========================================================================
#define BR 128
#define BC 128
#define SK 68
#define SV 133
#define SP 132
#define ATT_SMEM ((BC * SK + DK * SV + 8 * 16 * SP) * 4)   // 136448 B

__global__ __launch_bounds__(256) void attn_mma_kernel(
    const float* __restrict__ Q, const float* __restrict__ K,
    const float* __restrict__ V, float* __restrict__ O)
{
    extern __shared__ float sh[];
    float* Ks = sh;                    // [BC][SK]
    float* Vt = sh + BC * SK;          // [DK][SV]
    float* Ps = Vt + DK * SV;          // 8 warps x [16][SP]

    const int b  = blockIdx.z;
    const int h  = blockIdx.y;
    const int qt = (int)gridDim.x - 1 - (int)blockIdx.x;  // heavy tiles first
    const int q0 = qt * BR;
    const int t   = threadIdx.x;
    const int wid = t >> 5;
    const int lid = t & 31;
    const int g8  = lid >> 2;
    const int tig = lid & 3;

    // ---- Q fragments in registers (pre-scaled by 1/sqrt(dk)) ----
    uint32_t qf[8][4];
    {
        const float* qb = Q + (size_t)(b * SS + q0 + wid * 16) * DM + h * DK;
#pragma unroll
        for (int ks = 0; ks < 8; ks++) {
            const int c = ks * 8 + tig;
            qf[ks][0] = f2tf32(qb[(size_t)g8 * DM + c] * 0.125f);
            qf[ks][1] = f2tf32(qb[(size_t)(g8 + 8) * DM + c] * 0.125f);
            qf[ks][2] = f2tf32(qb[(size_t)g8 * DM + c + 4] * 0.125f);
            qf[ks][3] = f2tf32(qb[(size_t)(g8 + 8) * DM + c + 4] * 0.125f);
        }
    }

    float oacc[8][4];
#pragma unroll
    for (int nt = 0; nt < 8; nt++)
#pragma unroll
        for (int r = 0; r < 4; r++) oacc[nt][r] = 0.0f;
    float m_r[2] = {-INFINITY, -INFINITY};
    float l_r[2] = {0.0f, 0.0f};

    float* Pw = Ps + wid * 16 * SP;

    const int ntiles = qt + 1;
    for (int kt = 0; kt < ntiles; kt++) {
        const int kv0 = kt * BC;
        __syncthreads();   // everyone done reading Ks/Vt from prev iter

        // ---- Load K tile [BC][64] and V tile transposed [64][BC] ----
        {
            const float* kb = K + (size_t)(b * SS + kv0) * DM + h * DK;
            const float* vb = V + (size_t)(b * SS + kv0) * DM + h * DK;
#pragma unroll
            for (int i = 0; i < 8; i++) {
                const int idx = t + i * 256;       // 0..2047
                const int row = idx >> 4;          // kv row
                const int c4  = (idx & 15) * 4;    // d offset
                float4 kv4 = *(const float4*)&kb[(size_t)row * DM + c4];
                float4 vv4 = *(const float4*)&vb[(size_t)row * DM + c4];
                float* kd = &Ks[row * SK + c4];
                kd[0] = f2tf32f(kv4.x);
                kd[1] = f2tf32f(kv4.y);
                kd[2] = f2tf32f(kv4.z);
                kd[3] = f2tf32f(kv4.w);
                Vt[(c4 + 0) * SV + row] = f2tf32f(vv4.x);
                Vt[(c4 + 1) * SV + row] = f2tf32f(vv4.y);
                Vt[(c4 + 2) * SV + row] = f2tf32f(vv4.z);
                Vt[(c4 + 3) * SV + row] = f2tf32f(vv4.w);
            }
        }
        __syncthreads();

        // ---- S = (Q/8) K^T : m16 x n128 per warp ----
        float sacc[16][4];
#pragma unroll
        for (int nt = 0; nt < 16; nt++)
#pragma unroll
            for (int r = 0; r < 4; r++) sacc[nt][r] = 0.0f;

#pragma unroll
        for (int ks = 0; ks < 8; ks++) {
            const int k0 = ks * 8;
#pragma unroll
            for (int nt = 0; nt < 16; nt++) {
                const float* bp = &Ks[(nt * 8 + g8) * SK + k0 + tig];
                uint32_t bf[2] = { __float_as_uint(bp[0]),
                                   __float_as_uint(bp[4]) };
                mma_tf32(sacc[nt], qf[ks], bf);
            }
        }

        // ---- Causal mask (diagonal tile only) ----
        if (kt == ntiles - 1) {
#pragma unroll
            for (int nt = 0; nt < 16; nt++) {
#pragma unroll
                for (int r = 0; r < 4; r++) {
                    const int col = nt * 8 + tig * 2 + (r & 1);
                    const int row = wid * 16 + g8 + ((r & 2) ? 8 : 0);
                    if (col > row) sacc[nt][r] = -INFINITY;
                }
            }
        }

        // ---- Online softmax (two row-halves per thread) ----
#pragma unroll
        for (int rh = 0; rh < 2; rh++) {
            float mx = -INFINITY;
#pragma unroll
            for (int nt = 0; nt < 16; nt++)
                mx = fmaxf(mx, fmaxf(sacc[nt][rh * 2], sacc[nt][rh * 2 + 1]));
            mx = fmaxf(mx, __shfl_xor_sync(0xffffffffu, mx, 1));
            mx = fmaxf(mx, __shfl_xor_sync(0xffffffffu, mx, 2));
            const float mnew  = fmaxf(m_r[rh], mx);
            const float alpha = __expf(m_r[rh] - mnew);
            float rs = 0.0f;
#pragma unroll
            for (int nt = 0; nt < 16; nt++) {
                float p0 = __expf(sacc[nt][rh * 2]     - mnew);
                float p1 = __expf(sacc[nt][rh * 2 + 1] - mnew);
                sacc[nt][rh * 2]     = p0;
                sacc[nt][rh * 2 + 1] = p1;
                rs += p0 + p1;
            }
            rs += __shfl_xor_sync(0xffffffffu, rs, 1);
            rs += __shfl_xor_sync(0xffffffffu, rs, 2);
            l_r[rh] = l_r[rh] * alpha + rs;
            m_r[rh] = mnew;
#pragma unroll
            for (int nt = 0; nt < 8; nt++) {
                oacc[nt][rh * 2]     *= alpha;
                oacc[nt][rh * 2 + 1] *= alpha;
            }
        }

        // ---- P -> per-warp smem (tf32-rounded), acc layout -> A layout ----
#pragma unroll
        for (int nt = 0; nt < 16; nt++) {
            float2 v0 = { f2tf32f(sacc[nt][0]), f2tf32f(sacc[nt][1]) };
            float2 v1 = { f2tf32f(sacc[nt][2]), f2tf32f(sacc[nt][3]) };
            *(float2*)&Pw[g8 * SP + nt * 8 + tig * 2]       = v0;
            *(float2*)&Pw[(g8 + 8) * SP + nt * 8 + tig * 2] = v1;
        }
        __syncwarp();

        // ---- O += P V : m16 x n64 per warp, k = 128 ----
#pragma unroll
        for (int ks = 0; ks < 16; ks++) {
            const int k0 = ks * 8;
            uint32_t paf[4];
            paf[0] = __float_as_uint(Pw[g8 * SP + k0 + tig]);
            paf[1] = __float_as_uint(Pw[(g8 + 8) * SP + k0 + tig]);
            paf[2] = __float_as_uint(Pw[g8 * SP + k0 + tig + 4]);
            paf[3] = __float_as_uint(Pw[(g8 + 8) * SP + k0 + tig + 4]);
#pragma unroll
            for (int nt = 0; nt < 8; nt++) {
                const float* vp = &Vt[(nt * 8 + g8) * SV + k0 + tig];
                uint32_t bf[2] = { __float_as_uint(vp[0]),
                                   __float_as_uint(vp[4]) };
                mma_tf32(oacc[nt], paf, bf);
            }
        }
    }

    // ---- Normalize + write ----
    {
        const float inv0 = 1.0f / l_r[0];
        const float inv1 = 1.0f / l_r[1];
        float* o0 = O + (size_t)(b * SS + q0 + wid * 16 + g8) * DM + h * DK;
        float* o1 = O + (size_t)(b * SS + q0 + wid * 16 + g8 + 8) * DM + h * DK;
#pragma unroll
        for (int nt = 0; nt < 8; nt++) {
            float2 v0 = { oacc[nt][0] * inv0, oacc[nt][1] * inv0 };
            float2 v1 = { oacc[nt][2] * inv1, oacc[nt][3] * inv1 };
            *(float2*)&o0[nt * 8 + tig * 2] = v0;
            *(float2*)&o1[nt * 8 + tig * 2] = v1;
        }
    }
}

// ---------------------------------------------------------------------------
// Launch
// ---------------------------------------------------------------------------
extern "C" void kernel_launch(void* const* d_in, const int* in_sizes, int n_in,
                              void* d_out, int out_size)
{
    const float* x  = (const float*)d_in[0];
    const int*   tp = (const int*)d_in[1];
    const float* Wq = (const float*)d_in[2];
    const float* Wk = (const float*)d_in[3];
    const float* Wv = (const float*)d_in[4];
    const float* Wo = (const float*)d_in[5];
    float* out = (float*)d_out;

    float *gq, *gk, *gv, *ga;
    cudaGetSymbolAddress((void**)&gq, g_Q);
    cudaGetSymbolAddress((void**)&gk, g_K);
    cudaGetSymbolAddress((void**)&gv, g_V);
    cudaGetSymbolAddress((void**)&ga, g_A);

    cudaFuncSetAttribute(gemm_tc_kernel,
                         cudaFuncAttributeMaxDynamicSharedMemorySize, GEMM_SMEM);
    cudaFuncSetAttribute(attn_mma_kernel,
                         cudaFuncAttributeMaxDynamicSharedMemorySize, ATT_SMEM);

    // Fused QKV projection (z picks the weight/output)
    gemm_tc_kernel<<<dim3(DM / 128, MROWS / 128, 3), GT_THREADS, GEMM_SMEM>>>(
        x, Wq, Wk, Wv, gq, gk, gv);

    int rope_threads = MROWS * (DM / 2);
    rope_kernel<<<(rope_threads + 255) / 256, 256>>>(gq, gk, tp);

    attn_mma_kernel<<<dim3(SS / BR, NH, BB), 256, ATT_SMEM>>>(gq, gk, gv, ga);

    // Output projection
    gemm_tc_kernel<<<dim3(DM / 128, MROWS / 128, 1), GT_THREADS, GEMM_SMEM>>>(
        ga, Wo, Wo, Wo, out, out, out);
}